// round 5
// baseline (speedup 1.0000x reference)
#include <cuda_runtime.h>
#include <cuda_bf16.h>
#include <math.h>
#include <stdint.h>

#define N_NODES 100000
#define N_EDGES 3200000
#define K1 489

// ---------------- scratch (device globals; no allocation allowed) ----------
__device__ __align__(256) float g_p1[N_NODES * 64];
__device__ __align__(256) float g_a1[N_NODES * 64];
__device__ __align__(256) float g_p2[N_NODES * 32];
__device__ __align__(256) float g_a2[N_NODES * 32];
__device__ __align__(256) float g_p3[N_NODES * 2];
__device__ __align__(256) float g_a3[N_NODES * 2];
__device__ float g_dinv[N_NODES];

// CSR (incoming edges, unordered row placement)
__device__ int g_cnt[N_NODES];
__device__ int g_start[N_NODES];
__device__ int g_cursor[N_NODES];
__device__ int g_head;
__device__ int g_csr[N_EDGES];

// ---------------- CSR build -------------------------------------------------
__global__ void k_init() {
    int i = blockIdx.x * blockDim.x + threadIdx.x;
    if (i < N_NODES) g_cnt[i] = 0;
    if (i == 0) g_head = 0;
}

__global__ void k_cnt(const int* __restrict__ dst) {
    int e = blockIdx.x * blockDim.x + threadIdx.x;
    if (e < N_EDGES) atomicAdd(&g_cnt[dst[e]], 1);
}

__global__ void k_alloc() {
    int i = blockIdx.x * blockDim.x + threadIdx.x;
    if (i >= N_NODES) return;
    int c = g_cnt[i];
    int s = atomicAdd(&g_head, c);
    g_start[i]  = s;
    g_cursor[i] = s;
    g_dinv[i]   = rsqrtf((float)(c + 1));
}

__global__ void k_fill(const int* __restrict__ src, const int* __restrict__ dst) {
    int e = blockIdx.x * blockDim.x + threadIdx.x;
    if (e >= N_EDGES) return;
    int d = dst[e];
    int pos = atomicAdd(&g_cursor[d], 1);
    g_csr[pos] = src[e];
}

// ---------------- tf32 helpers ----------------------------------------------
__device__ __forceinline__ uint32_t f2tf32(float x) {
    uint32_t r;
    asm("cvt.rna.tf32.f32 %0, %1;" : "=r"(r) : "f"(x));
    return r;
}

__device__ __forceinline__ void mma_tf32(float c[4],
                                         uint32_t a0, uint32_t a1, uint32_t a2, uint32_t a3,
                                         uint32_t b0, uint32_t b1) {
    asm volatile(
        "mma.sync.aligned.m16n8k8.row.col.f32.tf32.tf32.f32 "
        "{%0,%1,%2,%3}, {%4,%5,%6,%7}, {%8,%9}, {%0,%1,%2,%3};"
        : "+f"(c[0]), "+f"(c[1]), "+f"(c[2]), "+f"(c[3])
        : "r"(a0), "r"(a1), "r"(a2), "r"(a3), "r"(b0), "r"(b1));
}

// ---------------- GEMM1 (tensor core, 3xTF32): p1 = dinv .* (x @ W1) --------
// Block tile 128(M) x 64(N), BK=32, 256 threads = 8 warps (4 Mwarp x 2 Nwarp),
// each warp 32x32 via 2x4 m16n8k8 atoms. 3-term tf32 split for fp32 accuracy.
// SMEM planes packed in fragment order: float4 {hi_k, hi_{k+4}, lo_k, lo_{k+4}}.
__global__ __launch_bounds__(256) void k_gemm1_tc(const float* __restrict__ X,
                                                  const float* __restrict__ W) {
    __shared__ uint32_t As[4 * 128 * 4 * 4];  // [ks][row][q][half] -> 32KB
    __shared__ uint32_t Bs[4 * 64 * 4 * 4];   // [ks][col][q][half] -> 16KB

    const int tid = threadIdx.x;
    const int wid = tid >> 5;
    const int l   = tid & 31;
    const int m0  = (wid & 3) * 32;     // warp M offset within tile
    const int n0  = (wid >> 2) * 32;    // warp N offset within tile
    const int blockM = blockIdx.x * 128;

    float acc[2][4][4];
#pragma unroll
    for (int i = 0; i < 2; i++)
#pragma unroll
        for (int j = 0; j < 4; j++)
#pragma unroll
            for (int k = 0; k < 4; k++) acc[i][j][k] = 0.f;

    for (int chunk = 0; chunk < 16; chunk++) {
        const int k0c = chunk * 32;
        // ---- fill A plane: 128 rows x 32 k ----
#pragma unroll
        for (int i = 0; i < 16; i++) {
            int e = tid + i * 256;            // 0..4095
            int row = e >> 5, c = e & 31;
            int r = blockM + row, k = k0c + c;
            float x = (r < N_NODES && k < K1) ? X[(long long)r * K1 + k] : 0.f;
            uint32_t hi = f2tf32(x);
            float lo = x - __uint_as_float(hi);
            uint32_t loi = f2tf32(lo);
            int ks = c >> 3, q = c & 3, half = (c >> 2) & 1;
            uint32_t* base = &As[(((ks * 128 + row) * 4 + q) << 2)];
            base[half]     = hi;
            base[half + 2] = loi;
        }
        // ---- fill B plane: 32 k x 64 n (B[n][k] = W[k][n]) ----
#pragma unroll
        for (int i = 0; i < 8; i++) {
            int e = tid + i * 256;            // 0..2047
            int c = e >> 6, n = e & 63;
            int k = k0c + c;
            float w = (k < K1) ? W[k * 64 + n] : 0.f;
            uint32_t hi = f2tf32(w);
            float lo = w - __uint_as_float(hi);
            uint32_t loi = f2tf32(lo);
            int ks = c >> 3, q = c & 3, half = (c >> 2) & 1;
            uint32_t* base = &Bs[(((ks * 64 + n) * 4 + q) << 2)];
            base[half]     = hi;
            base[half + 2] = loi;
        }
        __syncthreads();

        const float4* As4 = (const float4*)As;
        const float4* Bs4 = (const float4*)Bs;
#pragma unroll
        for (int ks = 0; ks < 4; ks++) {
            // A fragments for 2 m-atoms (hi & lo planes)
            float4 va0[2], va1[2];
#pragma unroll
            for (int ma = 0; ma < 2; ma++) {
                int row0 = m0 + ma * 16 + (l >> 2);
                va0[ma] = As4[(ks * 128 + row0) * 4 + (l & 3)];
                va1[ma] = As4[(ks * 128 + row0 + 8) * 4 + (l & 3)];
            }
            // B fragments for 4 n-atoms
            float4 vb[4];
#pragma unroll
            for (int na = 0; na < 4; na++) {
                int col = n0 + na * 8 + (l >> 2);
                vb[na] = Bs4[(ks * 64 + col) * 4 + (l & 3)];
            }
#pragma unroll
            for (int ma = 0; ma < 2; ma++) {
                uint32_t ah0 = __float_as_uint(va0[ma].x), ah1 = __float_as_uint(va1[ma].x);
                uint32_t ah2 = __float_as_uint(va0[ma].y), ah3 = __float_as_uint(va1[ma].y);
                uint32_t al0 = __float_as_uint(va0[ma].z), al1 = __float_as_uint(va1[ma].z);
                uint32_t al2 = __float_as_uint(va0[ma].w), al3 = __float_as_uint(va1[ma].w);
#pragma unroll
                for (int na = 0; na < 4; na++) {
                    uint32_t bh0 = __float_as_uint(vb[na].x), bh1 = __float_as_uint(vb[na].y);
                    uint32_t bl0 = __float_as_uint(vb[na].z), bl1 = __float_as_uint(vb[na].w);
                    mma_tf32(acc[ma][na], ah0, ah1, ah2, ah3, bh0, bh1);  // hi*hi
                    mma_tf32(acc[ma][na], al0, al1, al2, al3, bh0, bh1);  // lo*hi
                    mma_tf32(acc[ma][na], ah0, ah1, ah2, ah3, bl0, bl1);  // hi*lo
                }
            }
        }
        __syncthreads();
    }

    // ---- epilogue: scale by dinv[row], store p1 (fragment layout) ----
#pragma unroll
    for (int ma = 0; ma < 2; ma++) {
        int r0 = blockM + m0 + ma * 16 + (l >> 2);
        int r1 = r0 + 8;
        float s0 = (r0 < N_NODES) ? g_dinv[r0] : 0.f;
        float s1 = (r1 < N_NODES) ? g_dinv[r1] : 0.f;
#pragma unroll
        for (int na = 0; na < 4; na++) {
            int col = n0 + na * 8 + 2 * (l & 3);
            if (r0 < N_NODES) {
                float2 v = make_float2(acc[ma][na][0] * s0, acc[ma][na][1] * s0);
                *(float2*)&g_p1[(long long)r0 * 64 + col] = v;
            }
            if (r1 < N_NODES) {
                float2 v = make_float2(acc[ma][na][2] * s1, acc[ma][na][3] * s1);
                *(float2*)&g_p1[(long long)r1 * 64 + col] = v;
            }
        }
    }
}

// ---------------- gather: a[d] = p[d] + sum_{s in N(d)} p[s] ----------------
__global__ __launch_bounds__(256) void k_gather64() {
    int t = blockIdx.x * blockDim.x + threadIdx.x;
    int node = t >> 4, lane = t & 15;
    if (node >= N_NODES) return;
    const float4* P = (const float4*)g_p1;
    float4 v = P[node * 16 + lane];   // self loop
    int beg = g_start[node], n = g_cnt[node];
    int j = 0;
    for (; j + 4 <= n; j += 4) {
        int s0 = g_csr[beg + j],     s1 = g_csr[beg + j + 1];
        int s2 = g_csr[beg + j + 2], s3 = g_csr[beg + j + 3];
        float4 u0 = __ldg(P + s0 * 16 + lane);
        float4 u1 = __ldg(P + s1 * 16 + lane);
        float4 u2 = __ldg(P + s2 * 16 + lane);
        float4 u3 = __ldg(P + s3 * 16 + lane);
        v.x += (u0.x + u1.x) + (u2.x + u3.x);
        v.y += (u0.y + u1.y) + (u2.y + u3.y);
        v.z += (u0.z + u1.z) + (u2.z + u3.z);
        v.w += (u0.w + u1.w) + (u2.w + u3.w);
    }
    for (; j < n; j++) {
        int s = g_csr[beg + j];
        float4 u = __ldg(P + s * 16 + lane);
        v.x += u.x; v.y += u.y; v.z += u.z; v.w += u.w;
    }
    ((float4*)g_a1)[node * 16 + lane] = v;
}

__global__ __launch_bounds__(256) void k_gather32() {
    int t = blockIdx.x * blockDim.x + threadIdx.x;
    int node = t >> 3, lane = t & 7;
    if (node >= N_NODES) return;
    const float4* P = (const float4*)g_p2;
    float4 v = P[node * 8 + lane];
    int beg = g_start[node], n = g_cnt[node];
    int j = 0;
    for (; j + 4 <= n; j += 4) {
        int s0 = g_csr[beg + j],     s1 = g_csr[beg + j + 1];
        int s2 = g_csr[beg + j + 2], s3 = g_csr[beg + j + 3];
        float4 u0 = __ldg(P + s0 * 8 + lane);
        float4 u1 = __ldg(P + s1 * 8 + lane);
        float4 u2 = __ldg(P + s2 * 8 + lane);
        float4 u3 = __ldg(P + s3 * 8 + lane);
        v.x += (u0.x + u1.x) + (u2.x + u3.x);
        v.y += (u0.y + u1.y) + (u2.y + u3.y);
        v.z += (u0.z + u1.z) + (u2.z + u3.z);
        v.w += (u0.w + u1.w) + (u2.w + u3.w);
    }
    for (; j < n; j++) {
        int s = g_csr[beg + j];
        float4 u = __ldg(P + s * 8 + lane);
        v.x += u.x; v.y += u.y; v.z += u.z; v.w += u.w;
    }
    ((float4*)g_a2)[node * 8 + lane] = v;
}

__global__ __launch_bounds__(256) void k_gather2() {
    int node = blockIdx.x * blockDim.x + threadIdx.x;
    if (node >= N_NODES) return;
    const float2* P = (const float2*)g_p3;
    float2 v = P[node];
    int beg = g_start[node], n = g_cnt[node];
    int j = 0;
    for (; j + 4 <= n; j += 4) {
        int s0 = g_csr[beg + j],     s1 = g_csr[beg + j + 1];
        int s2 = g_csr[beg + j + 2], s3 = g_csr[beg + j + 3];
        float2 u0 = __ldg(P + s0), u1 = __ldg(P + s1);
        float2 u2 = __ldg(P + s2), u3 = __ldg(P + s3);
        v.x += (u0.x + u1.x) + (u2.x + u3.x);
        v.y += (u0.y + u1.y) + (u2.y + u3.y);
    }
    for (; j < n; j++) {
        float2 u = __ldg(P + g_csr[beg + j]);
        v.x += u.x; v.y += u.y;
    }
    ((float2*)g_a3)[node] = v;
}

// ---------------- GEMM2: p2 = dinv .* (relu(dinv.*a1 + b1) @ W2) -----------
__global__ void k_gemm2(const float* __restrict__ W2, const float* __restrict__ b1) {
    __shared__ float Ws[64 * 32];
    __shared__ float bs[64];
    int tid = threadIdx.x;
    for (int i = tid; i < 64 * 32; i += 256) Ws[i] = W2[i];
    if (tid < 64) bs[tid] = b1[tid];
    __syncthreads();
    int warp = tid >> 5, lane = tid & 31;
    int row = blockIdx.x * 8 + warp;
    if (row >= N_NODES) return;
    float dv = g_dinv[row];
    const float* a = g_a1 + (long long)row * 64;
    float r0 = fmaxf(fmaf(dv, a[lane],      bs[lane]),      0.f);
    float r1 = fmaxf(fmaf(dv, a[lane + 32], bs[lane + 32]), 0.f);
    float acc = 0.f;
#pragma unroll
    for (int k = 0; k < 32; k++) {
        float xv = __shfl_sync(0xffffffffu, r0, k);
        acc = fmaf(xv, Ws[k * 32 + lane], acc);
    }
#pragma unroll
    for (int k = 0; k < 32; k++) {
        float xv = __shfl_sync(0xffffffffu, r1, k);
        acc = fmaf(xv, Ws[(k + 32) * 32 + lane], acc);
    }
    g_p2[(long long)row * 32 + lane] = acc * dv;
}

// ---------------- GEMM3: p3 = dinv .* (relu(dinv.*a2 + b2) @ W3) -----------
__global__ void k_gemm3(const float* __restrict__ W3, const float* __restrict__ b2) {
    __shared__ float w3[64];
    __shared__ float bb[32];
    if (threadIdx.x < 64) w3[threadIdx.x] = W3[threadIdx.x];
    if (threadIdx.x < 32) bb[threadIdx.x] = b2[threadIdx.x];
    __syncthreads();
    int row = blockIdx.x * blockDim.x + threadIdx.x;
    if (row >= N_NODES) return;
    float dv = g_dinv[row];
    const float* a = g_a2 + (long long)row * 32;
    float acc0 = 0.f, acc1 = 0.f;
#pragma unroll
    for (int k = 0; k < 32; k++) {
        float h = fmaxf(fmaf(dv, a[k], bb[k]), 0.f);
        acc0 = fmaf(h, w3[k * 2],     acc0);
        acc1 = fmaf(h, w3[k * 2 + 1], acc1);
    }
    ((float2*)g_p3)[row] = make_float2(acc0 * dv, acc1 * dv);
}

// ---------------- final: out = log_softmax(dinv.*a3 + b3) ------------------
__global__ void k_out(const float* __restrict__ b3, float* __restrict__ out) {
    int i = blockIdx.x * blockDim.x + threadIdx.x;
    if (i >= N_NODES) return;
    float dv = g_dinv[i];
    float z0 = fmaf(dv, g_a3[2 * i],     __ldg(&b3[0]));
    float z1 = fmaf(dv, g_a3[2 * i + 1], __ldg(&b3[1]));
    float m = fmaxf(z0, z1);
    float lse = m + logf(expf(z0 - m) + expf(z1 - m));
    ((float2*)out)[i] = make_float2(z0 - lse, z1 - lse);
}

// ---------------- launch ----------------------------------------------------
extern "C" void kernel_launch(void* const* d_in, const int* in_sizes, int n_in,
                              void* d_out, int out_size) {
    const float* x  = (const float*)d_in[0];
    const int*   ei = (const int*)d_in[1];
    const float* W1 = (const float*)d_in[2];
    const float* b1 = (const float*)d_in[3];
    const float* W2 = (const float*)d_in[4];
    const float* b2 = (const float*)d_in[5];
    const float* W3 = (const float*)d_in[6];
    const float* b3 = (const float*)d_in[7];
    float* out = (float*)d_out;

    const int* src = ei;
    const int* dst = ei + N_EDGES;

    const int TB = 256;
    const int gN = (N_NODES + TB - 1) / TB;
    const int gE = (N_EDGES + TB - 1) / TB;

    // CSR build (also produces dinv)
    k_init<<<gN, TB>>>();
    k_cnt<<<gE, TB>>>(dst);
    k_alloc<<<gN, TB>>>();
    k_fill<<<gE, TB>>>(src, dst);

    // layer 1 (tensor-core GEMM)
    k_gemm1_tc<<<(N_NODES + 127) / 128, TB>>>(x, W1);
    k_gather64<<<(N_NODES * 16 + TB - 1) / TB, TB>>>();

    // layer 2
    k_gemm2<<<(N_NODES + 7) / 8, TB>>>(W2, b1);
    k_gather32<<<(N_NODES * 8 + TB - 1) / TB, TB>>>();

    // layer 3
    k_gemm3<<<gN, TB>>>(W3, b2);
    k_gather2<<<gN, TB>>>();

    // output
    k_out<<<gN, TB>>>(b3, out);
}

// round 6
// speedup vs baseline: 1.3749x; 1.3749x over previous
#include <cuda_runtime.h>
#include <cuda_bf16.h>
#include <math.h>
#include <stdint.h>

#define N_NODES 100000
#define N_EDGES 3200000
#define K1 489
#define GEMM1_BLOCKS ((N_NODES + 127) / 128)   // 782

// ---------------- scratch (device globals; no allocation allowed) ----------
__device__ __align__(256) float g_p1[N_NODES * 64];
__device__ __align__(256) float g_a1[N_NODES * 64];
__device__ __align__(256) float g_p2[N_NODES * 32];
__device__ __align__(256) float g_p3[N_NODES * 2];
__device__ float g_dinv[N_NODES];

// CSR (incoming edges, unordered row placement)
__device__ int g_cnt[N_NODES];
__device__ int g_start[N_NODES];
__device__ int g_cursor[N_NODES];
__device__ int g_head;
__device__ int g_csr[N_EDGES];

// ---------------- CSR build (head) ------------------------------------------
__global__ void k_init() {
    int i = blockIdx.x * blockDim.x + threadIdx.x;
    if (i < N_NODES) g_cnt[i] = 0;
    if (i == 0) g_head = 0;
}

__global__ void k_cnt(const int* __restrict__ dst) {
    int e = blockIdx.x * blockDim.x + threadIdx.x;
    if (e < N_EDGES) atomicAdd(&g_cnt[dst[e]], 1);
}

__global__ void k_alloc() {
    int i = blockIdx.x * blockDim.x + threadIdx.x;
    if (i >= N_NODES) return;
    int c = g_cnt[i];
    int s = atomicAdd(&g_head, c);
    g_start[i]  = s;
    g_cursor[i] = s;
    g_dinv[i]   = rsqrtf((float)(c + 1));   // +1 self loop
}

// ---------------- fused: GEMM1 (SIMT) blocks + CSR-fill blocks --------------
// blocks [0, GEMM1_BLOCKS)            : p1 = dinv .* (x @ W1)
// blocks [GEMM1_BLOCKS, +12500)       : csr fill (independent of gemm1)
__global__ __launch_bounds__(256) void k_gemm1_fill(const float* __restrict__ X,
                                                    const float* __restrict__ W,
                                                    const int* __restrict__ src,
                                                    const int* __restrict__ dst) {
    const int tid = threadIdx.x;

    if (blockIdx.x >= GEMM1_BLOCKS) {
        // ---- CSR fill path ----
        int e = (blockIdx.x - GEMM1_BLOCKS) * 256 + tid;
        if (e < N_EDGES) {
            int d = dst[e];
            int pos = atomicAdd(&g_cursor[d], 1);
            g_csr[pos] = src[e];
        }
        return;
    }

    // ---- GEMM1 path: 128x64 tile, 8x4 microtile, BK=16 ----
    __shared__ float Xs[16][132];
    __shared__ float Ws[16][64];
    const int tx = tid & 15;
    const int ty = tid >> 4;
    const int blockM = blockIdx.x * 128;

    float acc[8][4] = {};

    for (int k0 = 0; k0 < K1; k0 += 16) {
#pragma unroll
        for (int i = 0; i < 8; i++) {
            int e  = tid + i * 256;
            int kl = e & 15, ml = e >> 4;
            int r = blockM + ml, k = k0 + kl;
            Xs[kl][ml] = (r < N_NODES && k < K1) ? X[(long long)r * K1 + k] : 0.f;
        }
        {
            int kl = tid >> 4, nl = (tid & 15) * 4;
            int k = k0 + kl;
            float4 w = (k < K1) ? *(const float4*)&W[k * 64 + nl]
                                : make_float4(0.f, 0.f, 0.f, 0.f);
            *(float4*)&Ws[kl][nl] = w;
        }
        __syncthreads();
#pragma unroll
        for (int kk = 0; kk < 16; kk++) {
            float xv[8], wv[4];
            *(float4*)&xv[0] = *(const float4*)&Xs[kk][ty * 8];
            *(float4*)&xv[4] = *(const float4*)&Xs[kk][ty * 8 + 4];
            *(float4*)&wv[0] = *(const float4*)&Ws[kk][tx * 4];
#pragma unroll
            for (int i = 0; i < 8; i++)
#pragma unroll
                for (int j = 0; j < 4; j++)
                    acc[i][j] = fmaf(xv[i], wv[j], acc[i][j]);
        }
        __syncthreads();
    }
#pragma unroll
    for (int i = 0; i < 8; i++) {
        int r = blockM + ty * 8 + i;
        if (r < N_NODES) {
            float s = g_dinv[r];
            float4 v = make_float4(acc[i][0] * s, acc[i][1] * s,
                                   acc[i][2] * s, acc[i][3] * s);
            *(float4*)&g_p1[(long long)r * 64 + tx * 4] = v;
        }
    }
}

// ---------------- gather64: a1[d] = p1[d] + sum p1[s] -----------------------
__global__ __launch_bounds__(256) void k_gather64() {
    int t = blockIdx.x * blockDim.x + threadIdx.x;
    int node = t >> 4, lane = t & 15;
    if (node >= N_NODES) return;
    const float4* P = (const float4*)g_p1;
    float4 v = P[node * 16 + lane];   // self loop
    int beg = g_start[node], n = g_cnt[node];
    int j = 0;
    for (; j + 4 <= n; j += 4) {
        int s0 = g_csr[beg + j],     s1 = g_csr[beg + j + 1];
        int s2 = g_csr[beg + j + 2], s3 = g_csr[beg + j + 3];
        float4 u0 = __ldg(P + s0 * 16 + lane);
        float4 u1 = __ldg(P + s1 * 16 + lane);
        float4 u2 = __ldg(P + s2 * 16 + lane);
        float4 u3 = __ldg(P + s3 * 16 + lane);
        v.x += (u0.x + u1.x) + (u2.x + u3.x);
        v.y += (u0.y + u1.y) + (u2.y + u3.y);
        v.z += (u0.z + u1.z) + (u2.z + u3.z);
        v.w += (u0.w + u1.w) + (u2.w + u3.w);
    }
    for (; j < n; j++) {
        int s = g_csr[beg + j];
        float4 u = __ldg(P + s * 16 + lane);
        v.x += u.x; v.y += u.y; v.z += u.z; v.w += u.w;
    }
    ((float4*)g_a1)[node * 16 + lane] = v;
}

// ---------------- GEMM2: p2 = dinv .* (relu(dinv.*a1 + b1) @ W2) -----------
__global__ void k_gemm2(const float* __restrict__ W2, const float* __restrict__ b1) {
    __shared__ float Ws[64 * 32];
    __shared__ float bs[64];
    int tid = threadIdx.x;
    for (int i = tid; i < 64 * 32; i += 256) Ws[i] = W2[i];
    if (tid < 64) bs[tid] = b1[tid];
    __syncthreads();
    int warp = tid >> 5, lane = tid & 31;
    int row = blockIdx.x * 8 + warp;
    if (row >= N_NODES) return;
    float dv = g_dinv[row];
    const float* a = g_a1 + (long long)row * 64;
    float r0 = fmaxf(fmaf(dv, a[lane],      bs[lane]),      0.f);
    float r1 = fmaxf(fmaf(dv, a[lane + 32], bs[lane + 32]), 0.f);
    float acc = 0.f;
#pragma unroll
    for (int k = 0; k < 32; k++) {
        float xv = __shfl_sync(0xffffffffu, r0, k);
        acc = fmaf(xv, Ws[k * 32 + lane], acc);
    }
#pragma unroll
    for (int k = 0; k < 32; k++) {
        float xv = __shfl_sync(0xffffffffu, r1, k);
        acc = fmaf(xv, Ws[(k + 32) * 32 + lane], acc);
    }
    g_p2[(long long)row * 32 + lane] = acc * dv;
}

// ---------------- fused gather32 + GEMM3 ------------------------------------
// a2[node] aggregated in 8-lane groups, then p3 = dinv .* (relu(dinv.*a2+b2) @ W3)
// computed in-register with an 8-lane shuffle reduction.
__global__ __launch_bounds__(256) void k_gather32_gemm3(const float* __restrict__ W3,
                                                        const float* __restrict__ b2) {
    __shared__ float w3[64];
    __shared__ float bb[32];
    if (threadIdx.x < 64) w3[threadIdx.x] = W3[threadIdx.x];
    if (threadIdx.x < 32) bb[threadIdx.x] = b2[threadIdx.x];
    __syncthreads();

    int t = blockIdx.x * blockDim.x + threadIdx.x;
    int node = t >> 3, lane = t & 7;
    if (node >= N_NODES) return;
    const float4* P = (const float4*)g_p2;
    float4 v = P[node * 8 + lane];   // self loop
    int beg = g_start[node], n = g_cnt[node];
    int j = 0;
    for (; j + 4 <= n; j += 4) {
        int s0 = g_csr[beg + j],     s1 = g_csr[beg + j + 1];
        int s2 = g_csr[beg + j + 2], s3 = g_csr[beg + j + 3];
        float4 u0 = __ldg(P + s0 * 8 + lane);
        float4 u1 = __ldg(P + s1 * 8 + lane);
        float4 u2 = __ldg(P + s2 * 8 + lane);
        float4 u3 = __ldg(P + s3 * 8 + lane);
        v.x += (u0.x + u1.x) + (u2.x + u3.x);
        v.y += (u0.y + u1.y) + (u2.y + u3.y);
        v.z += (u0.z + u1.z) + (u2.z + u3.z);
        v.w += (u0.w + u1.w) + (u2.w + u3.w);
    }
    for (; j < n; j++) {
        int s = g_csr[beg + j];
        float4 u = __ldg(P + s * 8 + lane);
        v.x += u.x; v.y += u.y; v.z += u.z; v.w += u.w;
    }

    // fused GEMM3: this lane owns features k = lane*4 .. lane*4+3
    float dv = g_dinv[node];
    int k4 = lane * 4;
    float h0 = fmaxf(fmaf(dv, v.x, bb[k4 + 0]), 0.f);
    float h1 = fmaxf(fmaf(dv, v.y, bb[k4 + 1]), 0.f);
    float h2 = fmaxf(fmaf(dv, v.z, bb[k4 + 2]), 0.f);
    float h3 = fmaxf(fmaf(dv, v.w, bb[k4 + 3]), 0.f);
    float acc0 = h0 * w3[(k4 + 0) * 2]     + h1 * w3[(k4 + 1) * 2]
               + h2 * w3[(k4 + 2) * 2]     + h3 * w3[(k4 + 3) * 2];
    float acc1 = h0 * w3[(k4 + 0) * 2 + 1] + h1 * w3[(k4 + 1) * 2 + 1]
               + h2 * w3[(k4 + 2) * 2 + 1] + h3 * w3[(k4 + 3) * 2 + 1];
    // reduce across the 8-lane group
#pragma unroll
    for (int off = 4; off > 0; off >>= 1) {
        acc0 += __shfl_down_sync(0xffffffffu, acc0, off, 8);
        acc1 += __shfl_down_sync(0xffffffffu, acc1, off, 8);
    }
    if (lane == 0)
        ((float2*)g_p3)[node] = make_float2(acc0 * dv, acc1 * dv);
}

// ---------------- fused gather2 + log_softmax -------------------------------
__global__ __launch_bounds__(256) void k_gather2_out(const float* __restrict__ b3,
                                                     float* __restrict__ out) {
    int node = blockIdx.x * blockDim.x + threadIdx.x;
    if (node >= N_NODES) return;
    const float2* P = (const float2*)g_p3;
    float2 v = P[node];   // self loop
    int beg = g_start[node], n = g_cnt[node];
    int j = 0;
    for (; j + 4 <= n; j += 4) {
        int s0 = g_csr[beg + j],     s1 = g_csr[beg + j + 1];
        int s2 = g_csr[beg + j + 2], s3 = g_csr[beg + j + 3];
        float2 u0 = __ldg(P + s0), u1 = __ldg(P + s1);
        float2 u2 = __ldg(P + s2), u3 = __ldg(P + s3);
        v.x += (u0.x + u1.x) + (u2.x + u3.x);
        v.y += (u0.y + u1.y) + (u2.y + u3.y);
    }
    for (; j < n; j++) {
        float2 u = __ldg(P + g_csr[beg + j]);
        v.x += u.x; v.y += u.y;
    }
    float dv = g_dinv[node];
    float z0 = fmaf(dv, v.x, __ldg(&b3[0]));
    float z1 = fmaf(dv, v.y, __ldg(&b3[1]));
    float m = fmaxf(z0, z1);
    float lse = m + logf(expf(z0 - m) + expf(z1 - m));
    ((float2*)out)[node] = make_float2(z0 - lse, z1 - lse);
}

// ---------------- launch ----------------------------------------------------
extern "C" void kernel_launch(void* const* d_in, const int* in_sizes, int n_in,
                              void* d_out, int out_size) {
    const float* x  = (const float*)d_in[0];
    const int*   ei = (const int*)d_in[1];
    const float* W1 = (const float*)d_in[2];
    const float* b1 = (const float*)d_in[3];
    const float* W2 = (const float*)d_in[4];
    const float* b2 = (const float*)d_in[5];
    const float* W3 = (const float*)d_in[6];
    const float* b3 = (const float*)d_in[7];
    float* out = (float*)d_out;

    const int* src = ei;
    const int* dst = ei + N_EDGES;

    const int TB = 256;
    const int gN = (N_NODES + TB - 1) / TB;
    const int gE = (N_EDGES + TB - 1) / TB;   // 12500

    // CSR head
    k_init<<<gN, TB>>>();
    k_cnt<<<gE, TB>>>(dst);
    k_alloc<<<gN, TB>>>();

    // layer 1 GEMM overlapped with CSR fill (independent work, complementary pipes)
    k_gemm1_fill<<<GEMM1_BLOCKS + gE, TB>>>(x, W1, src, dst);
    k_gather64<<<(N_NODES * 16 + TB - 1) / TB, TB>>>();

    // layer 2
    k_gemm2<<<(N_NODES + 7) / 8, TB>>>(W2, b1);

    // layer 3 (gather32 + gemm3 fused)
    k_gather32_gemm3<<<(N_NODES * 8 + TB - 1) / TB, TB>>>(W3, b2);

    // output (gather2 + log_softmax fused)
    k_gather2_out<<<gN, TB>>>(b3, out);
}

// round 8
// speedup vs baseline: 1.4247x; 1.0362x over previous
#include <cuda_runtime.h>
#include <cuda_bf16.h>
#include <math.h>
#include <stdint.h>

#define N_NODES 100000
#define N_EDGES 3200000
#define K1 489
#define GEMM1_BLOCKS ((N_NODES + 127) / 128)   // 782

// ---------------- scratch (device globals; no allocation allowed) ----------
__device__ __align__(256) float g_p1[N_NODES * 64];
__device__ __align__(256) float g_a1[N_NODES * 64];
__device__ __align__(256) float g_p2[N_NODES * 32];
__device__ __align__(256) float g_p3[N_NODES * 2];
__device__ float g_dinv[N_NODES];

// CSR (incoming edges, unordered row placement)
__device__ int g_cnt[N_NODES];
__device__ int g_start[N_NODES];
__device__ int g_cursor[N_NODES];
__device__ int g_head;
__device__ int g_csr[N_EDGES];

// ---------------- f32x2 packed-FMA helpers ----------------------------------
__device__ __forceinline__ void fma2(unsigned long long& d,
                                     unsigned long long a,
                                     unsigned long long b) {
    asm("fma.rn.f32x2 %0, %1, %2, %0;" : "+l"(d) : "l"(a), "l"(b));
}
__device__ __forceinline__ unsigned long long splat2(float v) {
    unsigned long long r;
    asm("mov.b64 %0, {%1, %1};" : "=l"(r) : "f"(v));
    return r;
}
__device__ __forceinline__ float2 unpack2(unsigned long long v) {
    float2 r;
    asm("mov.b64 {%0, %1}, %2;" : "=f"(r.x), "=f"(r.y) : "l"(v));
    return r;
}

// ---------------- CSR build (head) ------------------------------------------
__global__ void k_init() {
    int i = blockIdx.x * blockDim.x + threadIdx.x;
    if (i < N_NODES) g_cnt[i] = 0;
    if (i == 0) g_head = 0;
}

__global__ void k_cnt(const int* __restrict__ dst) {
    int e = blockIdx.x * blockDim.x + threadIdx.x;
    if (e < N_EDGES) atomicAdd(&g_cnt[dst[e]], 1);
}

__global__ void k_alloc() {
    int i = blockIdx.x * blockDim.x + threadIdx.x;
    if (i >= N_NODES) return;
    int c = g_cnt[i];
    int s = atomicAdd(&g_head, c);
    g_start[i]  = s;
    g_cursor[i] = s;
    g_dinv[i]   = rsqrtf((float)(c + 1));   // +1 self loop
}

// ---------------- fused: GEMM1 (f32x2 SIMT) blocks + CSR-fill blocks --------
// blocks [0, GEMM1_BLOCKS)      : p1 = dinv .* (x @ W1), packed-pair FFMA2
// blocks [GEMM1_BLOCKS, +12500) : csr fill (independent of gemm1)
__global__ __launch_bounds__(256) void k_gemm1_fill(const float* __restrict__ X,
                                                    const float* __restrict__ W,
                                                    const int* __restrict__ src,
                                                    const int* __restrict__ dst) {
    const int tid = threadIdx.x;

    if (blockIdx.x >= GEMM1_BLOCKS) {
        // ---- CSR fill path ----
        int e = (blockIdx.x - GEMM1_BLOCKS) * 256 + tid;
        if (e < N_EDGES) {
            int d = dst[e];
            int pos = atomicAdd(&g_cursor[d], 1);
            g_csr[pos] = src[e];
        }
        return;
    }

    // ---- GEMM1 path: 128x64 tile, 8x4 microtile (m packed in pairs), BK=16 ----
    __shared__ float Xs[16][132];
    __shared__ float Ws[16][64];
    const int tx = tid & 15;
    const int ty = tid >> 4;
    const int blockM = blockIdx.x * 128;

    unsigned long long acc2[4][4] = {};   // [m-pair][n], each = {m even, m odd}

    for (int k0 = 0; k0 < K1; k0 += 16) {
#pragma unroll
        for (int i = 0; i < 8; i++) {
            int e  = tid + i * 256;
            int kl = e & 15, ml = e >> 4;
            int r = blockM + ml, k = k0 + kl;
            Xs[kl][ml] = (r < N_NODES && k < K1) ? X[(long long)r * K1 + k] : 0.f;
        }
        {
            int kl = tid >> 4, nl = (tid & 15) * 4;
            int k = k0 + kl;
            float4 w = (k < K1) ? *(const float4*)&W[k * 64 + nl]
                                : make_float4(0.f, 0.f, 0.f, 0.f);
            *(float4*)&Ws[kl][nl] = w;
        }
        __syncthreads();
#pragma unroll
        for (int kk = 0; kk < 16; kk++) {
            // A pairs: 8 m values = 4 packed b64 (adjacent m contiguous in smem)
            unsigned long long xp[4];
            *(float4*)&xp[0] = *(const float4*)&Xs[kk][ty * 8];
            *(float4*)&xp[2] = *(const float4*)&Xs[kk][ty * 8 + 4];
            // B splats
            float4 wv = *(const float4*)&Ws[kk][tx * 4];
            unsigned long long ws0 = splat2(wv.x), ws1 = splat2(wv.y);
            unsigned long long ws2 = splat2(wv.z), ws3 = splat2(wv.w);
#pragma unroll
            for (int ip = 0; ip < 4; ip++) {
                fma2(acc2[ip][0], xp[ip], ws0);
                fma2(acc2[ip][1], xp[ip], ws1);
                fma2(acc2[ip][2], xp[ip], ws2);
                fma2(acc2[ip][3], xp[ip], ws3);
            }
        }
        __syncthreads();
    }

    // epilogue: unpack m-pairs, scale by dinv, store
#pragma unroll
    for (int ip = 0; ip < 4; ip++) {
        int r0 = blockM + ty * 8 + ip * 2;
        int r1 = r0 + 1;
        float2 c0 = unpack2(acc2[ip][0]);
        float2 c1 = unpack2(acc2[ip][1]);
        float2 c2 = unpack2(acc2[ip][2]);
        float2 c3 = unpack2(acc2[ip][3]);
        if (r0 < N_NODES) {
            float s = g_dinv[r0];
            float4 v = make_float4(c0.x * s, c1.x * s, c2.x * s, c3.x * s);
            *(float4*)&g_p1[(long long)r0 * 64 + tx * 4] = v;
        }
        if (r1 < N_NODES) {
            float s = g_dinv[r1];
            float4 v = make_float4(c0.y * s, c1.y * s, c2.y * s, c3.y * s);
            *(float4*)&g_p1[(long long)r1 * 64 + tx * 4] = v;
        }
    }
}

// ---------------- gather64: a1[d] = p1[d] + sum p1[s] -----------------------
__global__ __launch_bounds__(256) void k_gather64() {
    int t = blockIdx.x * blockDim.x + threadIdx.x;
    int node = t >> 4, lane = t & 15;
    if (node >= N_NODES) return;
    const float4* P = (const float4*)g_p1;
    float4 v = P[node * 16 + lane];   // self loop
    int beg = g_start[node], n = g_cnt[node];
    int j = 0;
    for (; j + 4 <= n; j += 4) {
        int s0 = g_csr[beg + j],     s1 = g_csr[beg + j + 1];
        int s2 = g_csr[beg + j + 2], s3 = g_csr[beg + j + 3];
        float4 u0 = __ldg(P + s0 * 16 + lane);
        float4 u1 = __ldg(P + s1 * 16 + lane);
        float4 u2 = __ldg(P + s2 * 16 + lane);
        float4 u3 = __ldg(P + s3 * 16 + lane);
        v.x += (u0.x + u1.x) + (u2.x + u3.x);
        v.y += (u0.y + u1.y) + (u2.y + u3.y);
        v.z += (u0.z + u1.z) + (u2.z + u3.z);
        v.w += (u0.w + u1.w) + (u2.w + u3.w);
    }
    for (; j < n; j++) {
        int s = g_csr[beg + j];
        float4 u = __ldg(P + s * 16 + lane);
        v.x += u.x; v.y += u.y; v.z += u.z; v.w += u.w;
    }
    ((float4*)g_a1)[node * 16 + lane] = v;
}

// ---------------- GEMM2: p2 = dinv .* (relu(dinv.*a1 + b1) @ W2) -----------
__global__ void k_gemm2(const float* __restrict__ W2, const float* __restrict__ b1) {
    __shared__ float Ws[64 * 32];
    __shared__ float bs[64];
    int tid = threadIdx.x;
    for (int i = tid; i < 64 * 32; i += 256) Ws[i] = W2[i];
    if (tid < 64) bs[tid] = b1[tid];
    __syncthreads();
    int warp = tid >> 5, lane = tid & 31;
    int row = blockIdx.x * 8 + warp;
    if (row >= N_NODES) return;
    float dv = g_dinv[row];
    const float* a = g_a1 + (long long)row * 64;
    float r0 = fmaxf(fmaf(dv, a[lane],      bs[lane]),      0.f);
    float r1 = fmaxf(fmaf(dv, a[lane + 32], bs[lane + 32]), 0.f);
    float acc = 0.f;
#pragma unroll
    for (int k = 0; k < 32; k++) {
        float xv = __shfl_sync(0xffffffffu, r0, k);
        acc = fmaf(xv, Ws[k * 32 + lane], acc);
    }
#pragma unroll
    for (int k = 0; k < 32; k++) {
        float xv = __shfl_sync(0xffffffffu, r1, k);
        acc = fmaf(xv, Ws[(k + 32) * 32 + lane], acc);
    }
    g_p2[(long long)row * 32 + lane] = acc * dv;
}

// ---------------- fused gather32 + GEMM3 ------------------------------------
__global__ __launch_bounds__(256) void k_gather32_gemm3(const float* __restrict__ W3,
                                                        const float* __restrict__ b2) {
    __shared__ float w3[64];
    __shared__ float bb[32];
    if (threadIdx.x < 64) w3[threadIdx.x] = W3[threadIdx.x];
    if (threadIdx.x < 32) bb[threadIdx.x] = b2[threadIdx.x];
    __syncthreads();

    int t = blockIdx.x * blockDim.x + threadIdx.x;
    int node = t >> 3, lane = t & 7;
    if (node >= N_NODES) return;
    const float4* P = (const float4*)g_p2;
    float4 v = P[node * 8 + lane];   // self loop
    int beg = g_start[node], n = g_cnt[node];
    int j = 0;
    for (; j + 4 <= n; j += 4) {
        int s0 = g_csr[beg + j],     s1 = g_csr[beg + j + 1];
        int s2 = g_csr[beg + j + 2], s3 = g_csr[beg + j + 3];
        float4 u0 = __ldg(P + s0 * 8 + lane);
        float4 u1 = __ldg(P + s1 * 8 + lane);
        float4 u2 = __ldg(P + s2 * 8 + lane);
        float4 u3 = __ldg(P + s3 * 8 + lane);
        v.x += (u0.x + u1.x) + (u2.x + u3.x);
        v.y += (u0.y + u1.y) + (u2.y + u3.y);
        v.z += (u0.z + u1.z) + (u2.z + u3.z);
        v.w += (u0.w + u1.w) + (u2.w + u3.w);
    }
    for (; j < n; j++) {
        int s = g_csr[beg + j];
        float4 u = __ldg(P + s * 8 + lane);
        v.x += u.x; v.y += u.y; v.z += u.z; v.w += u.w;
    }

    float dv = g_dinv[node];
    int k4 = lane * 4;
    float h0 = fmaxf(fmaf(dv, v.x, bb[k4 + 0]), 0.f);
    float h1 = fmaxf(fmaf(dv, v.y, bb[k4 + 1]), 0.f);
    float h2 = fmaxf(fmaf(dv, v.z, bb[k4 + 2]), 0.f);
    float h3 = fmaxf(fmaf(dv, v.w, bb[k4 + 3]), 0.f);
    float acc0 = h0 * w3[(k4 + 0) * 2]     + h1 * w3[(k4 + 1) * 2]
               + h2 * w3[(k4 + 2) * 2]     + h3 * w3[(k4 + 3) * 2];
    float acc1 = h0 * w3[(k4 + 0) * 2 + 1] + h1 * w3[(k4 + 1) * 2 + 1]
               + h2 * w3[(k4 + 2) * 2 + 1] + h3 * w3[(k4 + 3) * 2 + 1];
#pragma unroll
    for (int off = 4; off > 0; off >>= 1) {
        acc0 += __shfl_down_sync(0xffffffffu, acc0, off, 8);
        acc1 += __shfl_down_sync(0xffffffffu, acc1, off, 8);
    }
    if (lane == 0)
        ((float2*)g_p3)[node] = make_float2(acc0 * dv, acc1 * dv);
}

// ---------------- fused gather2 + log_softmax -------------------------------
__global__ __launch_bounds__(256) void k_gather2_out(const float* __restrict__ b3,
                                                     float* __restrict__ out) {
    int node = blockIdx.x * blockDim.x + threadIdx.x;
    if (node >= N_NODES) return;
    const float2* P = (const float2*)g_p3;
    float2 v = P[node];   // self loop
    int beg = g_start[node], n = g_cnt[node];
    int j = 0;
    for (; j + 4 <= n; j += 4) {
        int s0 = g_csr[beg + j],     s1 = g_csr[beg + j + 1];
        int s2 = g_csr[beg + j + 2], s3 = g_csr[beg + j + 3];
        float2 u0 = __ldg(P + s0), u1 = __ldg(P + s1);
        float2 u2 = __ldg(P + s2), u3 = __ldg(P + s3);
        v.x += (u0.x + u1.x) + (u2.x + u3.x);
        v.y += (u0.y + u1.y) + (u2.y + u3.y);
    }
    for (; j < n; j++) {
        float2 u = __ldg(P + g_csr[beg + j]);
        v.x += u.x; v.y += u.y;
    }
    float dv = g_dinv[node];
    float z0 = fmaf(dv, v.x, __ldg(&b3[0]));
    float z1 = fmaf(dv, v.y, __ldg(&b3[1]));
    float m = fmaxf(z0, z1);
    float lse = m + logf(expf(z0 - m) + expf(z1 - m));
    ((float2*)out)[node] = make_float2(z0 - lse, z1 - lse);
}

// ---------------- launch ----------------------------------------------------
extern "C" void kernel_launch(void* const* d_in, const int* in_sizes, int n_in,
                              void* d_out, int out_size) {
    const float* x  = (const float*)d_in[0];
    const int*   ei = (const int*)d_in[1];
    const float* W1 = (const float*)d_in[2];
    const float* b1 = (const float*)d_in[3];
    const float* W2 = (const float*)d_in[4];
    const float* b2 = (const float*)d_in[5];
    const float* W3 = (const float*)d_in[6];
    const float* b3 = (const float*)d_in[7];
    float* out = (float*)d_out;

    const int* src = ei;
    const int* dst = ei + N_EDGES;

    const int TB = 256;
    const int gN = (N_NODES + TB - 1) / TB;
    const int gE = (N_EDGES + TB - 1) / TB;   // 12500

    // CSR head
    k_init<<<gN, TB>>>();
    k_cnt<<<gE, TB>>>(dst);
    k_alloc<<<gN, TB>>>();

    // layer 1 GEMM (f32x2 packed FMA) overlapped with CSR fill
    k_gemm1_fill<<<GEMM1_BLOCKS + gE, TB>>>(x, W1, src, dst);
    k_gather64<<<(N_NODES * 16 + TB - 1) / TB, TB>>>();

    // layer 2
    k_gemm2<<<(N_NODES + 7) / 8, TB>>>(W2, b1);

    // layer 3 (gather32 + gemm3 fused)
    k_gather32_gemm3<<<(N_NODES * 8 + TB - 1) / TB, TB>>>(W3, b2);

    // output (gather2 + log_softmax fused)
    k_gather2_out<<<gN, TB>>>(b3, out);
}